// round 11
// baseline (speedup 1.0000x reference)
#include <cuda_runtime.h>

// ---------------------------------------------------------------------------
// ISTFT fused: B=16, NFREQ=513, T=2048, NFFT=1024, HOP=256, WIN=1024, PAD=384
// Kernel A: zero exactly the atomic-stripe samples (compact index mapping).
// Kernel B: 16 frames/block in TWO 8-frame passes. Merged float2 spectrum
//           loads (halves global L1 wavefronts), per-pass real-packed 512-pt
//           radix-8 Stockham inverse FFT (float2 shared, register twiddles,
//           R8-style flat packing), windowed frames -> 16-row y in shared,
//           overlap-add direct to out (interior float2 stores, stripe
//           atomicAdds, explicit envelope at batch edges). No global scratch.
// ---------------------------------------------------------------------------

#define BATCH     16
#define NFREQ     513
#define TT        2048
#define NFFT      1024
#define HOP       256
#define PAD       384
#define OUT_PER_B 524288                 // (T-1)*HOP + WIN - 2*PAD = 1<<19
#define NFRAMES   (BATCH * TT)           // 32768
#define FPB       16                     // frames per block (2 FFT passes)
#define YPITCH    1028                   // 1028 % 32 == 4 -> bank-perm rows
#define REGION    8224                   // 8*YPITCH floats; >= 8192 A floats

#define SM_FLOATS (2 * REGION + 16)      // two pass regions + Nyquist buffer
#define SM_BYTES  (SM_FLOATS * 4)        // 65856 bytes -> 3 blocks/SM

// conflict-free shared index (float2 units): phi(pos) = pos ^ (pos>>3)
__device__ __forceinline__ int sidx(int pos, int f) {
    return ((pos ^ (pos >> 3)) << 3) | f;
}

// radix-8 butterfly on 8 complex registers (inverse FFT, +i convention)
__device__ __forceinline__ void bfly8(const float* xr, const float* xi,
                                      float* Xr, float* Xi)
{
    float e0r = xr[0] + xr[4], e0i = xi[0] + xi[4];
    float e1r = xr[0] - xr[4], e1i = xi[0] - xi[4];
    float e2r = xr[2] + xr[6], e2i = xi[2] + xi[6];
    float e3r = xr[2] - xr[6], e3i = xi[2] - xi[6];
    float E0r = e0r + e2r, E0i = e0i + e2i;
    float E2r = e0r - e2r, E2i = e0i - e2i;
    float E1r = e1r - e3i, E1i = e1i + e3r;
    float E3r = e1r + e3i, E3i = e1i - e3r;

    float o0r = xr[1] + xr[5], o0i = xi[1] + xi[5];
    float o1r = xr[1] - xr[5], o1i = xi[1] - xi[5];
    float o2r = xr[3] + xr[7], o2i = xi[3] + xi[7];
    float o3r = xr[3] - xr[7], o3i = xi[3] - xi[7];
    float O0r = o0r + o2r, O0i = o0i + o2i;
    float O2r = o0r - o2r, O2i = o0i - o2i;
    float O1r = o1r - o3i, O1i = o1i + o3r;
    float O3r = o1r + o3i, O3i = o1i - o3r;

    const float RS = 0.70710678118654752440f;
    float c1r = RS * (O1r - O1i), c1i = RS * (O1r + O1i);   // e^{+i pi/4} O1
    float c2r = -O2i,             c2i = O2r;                // i * O2
    float c3r = -RS * (O3r + O3i), c3i = RS * (O3r - O3i);  // e^{+3i pi/4} O3

    Xr[0] = E0r + O0r; Xi[0] = E0i + O0i;
    Xr[4] = E0r - O0r; Xi[4] = E0i - O0i;
    Xr[1] = E1r + c1r; Xi[1] = E1i + c1i;
    Xr[5] = E1r - c1r; Xi[5] = E1i - c1i;
    Xr[2] = E2r + c2r; Xi[2] = E2i + c2i;
    Xr[6] = E2r - c2r; Xi[6] = E2i - c2i;
    Xr[3] = E3r + c3r; Xi[3] = E3i + c3i;
    Xr[7] = E3r - c3r; Xi[7] = E3i - c3i;
}

// zero exactly the stripe float4s: per batch 96 head + 127*192 = 24480
__global__ void __launch_bounds__(256)
istft_zero_kernel(float4* __restrict__ out4)
{
    unsigned idx = blockIdx.x * 256u + threadIdx.x;   // < 391680 exactly
    unsigned b = idx / 24480u;
    unsigned r = idx - b * 24480u;
    unsigned o4;
    if (r < 96u) {
        o4 = r;                                       // head: o in [0,384)
    } else {
        unsigned rr = r - 96u;
        unsigned j  = rr / 192u + 1u;                 // 16-frame period 1..127
        unsigned t  = rr - (j - 1u) * 192u;
        o4 = 1024u * j - 96u + t;                     // o in [4096j-384, +768)
    }
    out4[b * 131072u + o4] = make_float4(0.f, 0.f, 0.f, 0.f);
}

__global__ void __launch_bounds__(512, 3)
istft_fused_kernel(const float* __restrict__ spr,
                   const float* __restrict__ spi,
                   const float* __restrict__ win,
                   float* __restrict__ out)
{
    extern __shared__ float sm[];
    float* x512buf = sm + 2 * REGION;   // 16 floats: Nyquist re per frame
    float* y       = sm;                // 16 rows x YPITCH (uniform stride)

    const int tid = threadIdx.x;
    const int f   = tid & 7;    // frame lane (within a pass)
    const int u   = tid >> 3;   // worker 0..63

    const int fr0 = blockIdx.x * FPB;
    const int b   = fr0 >> 11;
    const int t0  = fr0 & 2047;

    // register twiddle bases (shared by both passes)
    float zwr, zwi;   // e^{+2pi i u/1024}
    __sincosf((float)u * 6.1359231515e-3f, &zwi, &zwr);
    float w1r = fmaf(zwr, zwr, -zwi * zwi);   // e^{+2pi i u/512}
    float w1i = 2.0f * zwr * zwi;
    const int h = u >> 3;
    float bhr, bhi;   // e^{+2pi i h/64}
    __sincosf((float)h * 9.8174770424e-2f, &bhi, &bhr);

    // ---- merged spectrum load: float2 t-pairs scattered to both regions ----
    // lane f holds frames 2f, 2f+1 (abs 0..15); pass-1 lanes permuted by XOR 1
    {
        const float2* pr2 = (const float2*)(spr + (size_t)b * NFREQ * TT + t0) + f;
        const float2* pi2 = (const float2*)(spi + (size_t)b * NFREQ * TT + t0) + f;
        float* Ap = (f < 4) ? sm : (sm + REGION);
        const int g0 = (2 * f) & 7;
        const int l0 = (f < 4) ? g0 : (g0 ^ 1);   // dest lane of .x
        const int l1 = l0 ^ 1;                    // dest lane of .y
        #pragma unroll
        for (int m = 0; m < 8; m++) {
            int k = u + (m << 6);
            float2 re = __ldg(pr2 + k * 1024);
            float2 im = __ldg(pi2 + k * 1024);
            int s0 = sidx(k, l0) * 2;
            int s1 = sidx(k, l1) * 2;
            Ap[s0] = re.x;  Ap[s0 + 1] = im.x;
            Ap[s1] = re.y;  Ap[s1 + 1] = im.y;
        }
        if (u == 0) {
            float2 re = __ldg(pr2 + 512 * 1024);
            x512buf[2 * f]     = re.x;
            x512buf[2 * f + 1] = re.y;
        }
    }
    __syncthreads();

    // ============ two 8-frame FFT passes ============
    #pragma unroll
    for (int p = 0; p < 2; p++) {
        float2* A = (float2*)(sm + p * REGION);
        const int frow = p ? (8 + (f ^ 1)) : f;   // absolute y row 0..15
        float vr[8], vi[8];

        // ---- Hermitian packing Z[k]=E+iO (k=u+64m) into registers ----
        {
            float x512 = x512buf[frow];
            float ct = zwr, st = zwi;
            const float S16r = 0.92387953251128675613f;
            const float S16i = 0.38268343236508977173f;
            #pragma unroll
            for (int m = 0; m < 8; m++) {
                int k = u + (m << 6);
                float2 zk = A[sidx(k, f)];
                float xcr, xci;
                if (k == 0) { zk.y = 0.0f; xcr = x512; xci = 0.0f; }
                else { float2 zc = A[sidx(512 - k, f)]; xcr = zc.x; xci = zc.y; }
                float Er = 0.5f * (zk.x + xcr);
                float Ei = 0.5f * (zk.y - xci);
                float Dr = 0.5f * (zk.x - xcr);
                float Di = 0.5f * (zk.y + xci);
                float Or = fmaf(ct, Dr, -st * Di);
                float Oi = fmaf(ct, Di,  st * Dr);
                vr[m] = Er - Oi;
                vi[m] = Ei + Or;
                float nc = fmaf(ct, S16r, -st * S16i);
                float ns = fmaf(ct, S16i,  st * S16r);
                ct = nc; st = ns;
            }
        }
        __syncthreads();   // packing reads done -> safe to overwrite A

        // ---- stage 1 (S=1): regs -> A, twiddle w1^m ----
        {
            float Xr[8], Xi[8];
            bfly8(vr, vi, Xr, Xi);
            A[sidx(8 * u, f)] = make_float2(Xr[0], Xi[0]);
            float cr = w1r, ci = w1i;
            #pragma unroll
            for (int m = 1; m < 8; m++) {
                A[sidx(8 * u + m, f)] =
                    make_float2(fmaf(Xr[m], cr, -Xi[m] * ci),
                                fmaf(Xr[m], ci,  Xi[m] * cr));
                float nc = fmaf(cr, w1r, -ci * w1i);
                float ns = fmaf(cr, w1i,  ci * w1r);
                cr = nc; ci = ns;
            }
        }
        __syncthreads();

        // ---- stage 2 (S=8): A -> regs -> A, twiddle bh^m ----
        {
            #pragma unroll
            for (int j = 0; j < 8; j++) {
                float2 z = A[sidx(u + (j << 6), f)];
                vr[j] = z.x; vi[j] = z.y;
            }
            __syncthreads();
            float Xr[8], Xi[8];
            bfly8(vr, vi, Xr, Xi);
            const int wb = (u & 7) + 64 * h;
            A[sidx(wb, f)] = make_float2(Xr[0], Xi[0]);
            float cr = bhr, ci = bhi;
            #pragma unroll
            for (int m = 1; m < 8; m++) {
                A[sidx(wb + 8 * m, f)] =
                    make_float2(fmaf(Xr[m], cr, -Xi[m] * ci),
                                fmaf(Xr[m], ci,  Xi[m] * cr));
                float nc = fmaf(cr, bhr, -ci * bhi);
                float ns = fmaf(cr, bhi,  ci * bhr);
                cr = nc; ci = ns;
            }
        }
        __syncthreads();

        // ---- stage 3 (S=64): A -> regs; windowed frame -> y[frow] ----
        #pragma unroll
        for (int j = 0; j < 8; j++) {
            float2 z = A[sidx(u + (j << 6), f)];
            vr[j] = z.x; vi[j] = z.y;
        }
        __syncthreads();   // reads done -> y row may overwrite A
        {
            float Xr[8], Xi[8];
            bfly8(vr, vi, Xr, Xi);
            const float2* w2 = (const float2*)win;
            const float inv = 1.0f / 512.0f;
            float* yf = y + frow * YPITCH;
            #pragma unroll
            for (int m = 0; m < 8; m++) {
                int n = u + (m << 6);
                float2 wv = __ldg(w2 + n);
                float2 o;
                o.x = Xr[m] * inv * wv.x;
                o.y = Xi[m] * inv * wv.y;
                *(float2*)(yf + 2 * n) = o;    // pos 2n, 2n+1
            }
        }
        __syncthreads();
    }

    // =================== overlap-add from shared ===================
    float* outb = out + (size_t)b * OUT_PER_B;
    const float TW3 = 2.0f / 3.0f;

    // interior-owned: tmax in [t0+3, t0+15]; 3328 samples as 1664 float2
    for (int s2 = tid; s2 < 1664; s2 += 512) {
        int fl  = 3 + (s2 >> 7);           // 3..15
        int pos = (s2 & 127) << 1;
        const float* yb = y + pos;
        float2 a0 = *(const float2*)(yb + (fl - 3) * YPITCH + 768);
        float2 a1 = *(const float2*)(yb + (fl - 2) * YPITCH + 512);
        float2 a2 = *(const float2*)(yb + (fl - 1) * YPITCH + 256);
        float2 a3 = *(const float2*)(yb +  fl      * YPITCH);
        float2 r;
        r.x = (a0.x + a1.x + a2.x + a3.x) * TW3;
        r.y = (a0.y + a1.y + a2.y + a3.y) * TW3;
        *(float2*)(outb + ((t0 + fl) << 8) + pos - PAD) = r;
    }

    if (t0 != 0) {
        // bottom stripe: l in [256 t0, 256 t0 + 768)
        for (int s = tid; s < 768; s += 512) {
            int r = s >> 8;                // tmax - t0: 0,1,2
            float acc = y[s];
            if (r >= 1) acc += y[YPITCH + s - 256];
            if (r >= 2) acc += y[2 * YPITCH + s - 512];
            atomicAdd(outb + (t0 << 8) + s - PAD, acc * TW3);
        }
    } else {
        // batch start: l in [384, 768), env varies
        if (tid < 384) {
            int l = PAD + tid;
            int tmax = l >> 8;             // 1 or 2
            float acc = 0.0f, env = 0.0f;
            for (int t = 0; t <= tmax; t++) {
                int pos = l - (t << 8);
                float wv = __ldg(win + pos);
                env = fmaf(wv, wv, env);
                acc += y[t * YPITCH + pos];
            }
            outb[l - PAD] = acc / env;
        }
    }

    if (t0 != 2032) {
        // top stripe: l in [256(t0+16), +768)
        for (int s = tid; s < 768; s += 512) {
            int r = s >> 8;                // 0,1,2 ; count = 3 - r
            float acc = y[15 * YPITCH + s + 256];
            if (r <= 1) acc += y[14 * YPITCH + s + 512];
            if (r == 0) acc += y[13 * YPITCH + s + 768];
            atomicAdd(outb + ((t0 + 16) << 8) + s - PAD, acc * TW3);
        }
    } else {
        // batch end: l in [524288, 524672)
        if (tid < 384) {
            int l = 524288 + tid;
            int tmin = (l - 768) >> 8;     // 2045..2046
            float acc = 0.0f, env = 0.0f;
            for (int t = tmin; t <= 2047; t++) {
                int pos = l - (t << 8);
                float wv = __ldg(win + pos);
                env = fmaf(wv, wv, env);
                acc += y[(t - 2032) * YPITCH + pos];
            }
            outb[l - PAD] = acc / env;
        }
    }
}

extern "C" void kernel_launch(void* const* d_in, const int* in_sizes, int n_in,
                              void* d_out, int out_size)
{
    const float* spr = (const float*)d_in[0];
    const float* spi = (const float*)d_in[1];
    const float* win = (const float*)d_in[2];
    float* out = (float*)d_out;

    cudaFuncSetAttribute(istft_fused_kernel,
                         cudaFuncAttributeMaxDynamicSharedMemorySize, SM_BYTES);

    istft_zero_kernel<<<1530, 256>>>((float4*)out);
    istft_fused_kernel<<<NFRAMES / FPB, 512, SM_BYTES>>>(spr, spi, win, out);
}

// round 12
// speedup vs baseline: 1.5984x; 1.5984x over previous
#include <cuda_runtime.h>

// ---------------------------------------------------------------------------
// ISTFT fused: B=16, NFREQ=513, T=2048, NFFT=1024, HOP=256, WIN=1024, PAD=384
// Kernel A: zero exactly the atomic-stripe samples (compact index mapping).
// Kernel B: 8 frames/block, real-packed 512-pt radix-8 Stockham inverse FFT
//           with float2-interleaved shared (LDS.64/STS.64, conflict-free
//           swizzle) and register-computed twiddles; windowed frames staged
//           in shared; overlap-add direct to out (float2 stores interior,
//           2-way atomicAdd stripes, explicit env at batch edges).
//           No global scratch.
// ---------------------------------------------------------------------------

#define BATCH     16
#define NFREQ     513
#define TT        2048
#define NFFT      1024
#define HOP       256
#define PAD       384
#define OUT_PER_B 524288                 // (T-1)*HOP + WIN - 2*PAD = 1<<19
#define NFRAMES   (BATCH * TT)           // 32768
#define FPB       8                      // frames per block
#define YPITCH    1028                   // 1028 % 32 == 4 -> bank-perm rows

#define SM_FLOATS (FPB * YPITCH + 8)     // max(A: 8192, y: 8224)
#define SM_BYTES  (SM_FLOATS * 4)        // 32928 bytes

// conflict-free shared index (float2 units): phi(pos) = pos ^ (pos>>3)
__device__ __forceinline__ int sidx(int pos, int f) {
    return ((pos ^ (pos >> 3)) << 3) | f;
}

// radix-8 butterfly on 8 complex registers (inverse FFT, +i convention)
__device__ __forceinline__ void bfly8(const float* xr, const float* xi,
                                      float* Xr, float* Xi)
{
    float e0r = xr[0] + xr[4], e0i = xi[0] + xi[4];
    float e1r = xr[0] - xr[4], e1i = xi[0] - xi[4];
    float e2r = xr[2] + xr[6], e2i = xi[2] + xi[6];
    float e3r = xr[2] - xr[6], e3i = xi[2] - xi[6];
    float E0r = e0r + e2r, E0i = e0i + e2i;
    float E2r = e0r - e2r, E2i = e0i - e2i;
    float E1r = e1r - e3i, E1i = e1i + e3r;
    float E3r = e1r + e3i, E3i = e1i - e3r;

    float o0r = xr[1] + xr[5], o0i = xi[1] + xi[5];
    float o1r = xr[1] - xr[5], o1i = xi[1] - xi[5];
    float o2r = xr[3] + xr[7], o2i = xi[3] + xi[7];
    float o3r = xr[3] - xr[7], o3i = xi[3] - xi[7];
    float O0r = o0r + o2r, O0i = o0i + o2i;
    float O2r = o0r - o2r, O2i = o0i - o2i;
    float O1r = o1r - o3i, O1i = o1i + o3r;
    float O3r = o1r + o3i, O3i = o1i - o3r;

    const float RS = 0.70710678118654752440f;
    float c1r = RS * (O1r - O1i), c1i = RS * (O1r + O1i);   // e^{+i pi/4} O1
    float c2r = -O2i,             c2i = O2r;                // i * O2
    float c3r = -RS * (O3r + O3i), c3i = RS * (O3r - O3i);  // e^{+3i pi/4} O3

    Xr[0] = E0r + O0r; Xi[0] = E0i + O0i;
    Xr[4] = E0r - O0r; Xi[4] = E0i - O0i;
    Xr[1] = E1r + c1r; Xi[1] = E1i + c1i;
    Xr[5] = E1r - c1r; Xi[5] = E1i - c1i;
    Xr[2] = E2r + c2r; Xi[2] = E2i + c2i;
    Xr[6] = E2r - c2r; Xi[6] = E2i - c2i;
    Xr[3] = E3r + c3r; Xi[3] = E3i + c3i;
    Xr[7] = E3r - c3r; Xi[7] = E3i - c3i;
}

// zero exactly the stripe float4s: per batch 96 + 255*192 + 96 = 49152
__global__ void __launch_bounds__(256)
istft_zero_kernel(float4* __restrict__ out4)
{
    unsigned idx = blockIdx.x * 256u + threadIdx.x;   // < 786432
    unsigned b = idx / 49152u;
    unsigned r = idx - b * 49152u;
    unsigned o4;
    if (r < 96u) {
        o4 = r;                                       // head: o in [0,384)
    } else {
        unsigned rr = r - 96u;
        unsigned k  = rr / 192u + 1u;                 // 8-frame period 1..256
        unsigned j  = rr - (k - 1u) * 192u;
        o4 = (k << 9) - 96u + j;                      // o in [2048k-384, +768)
    }
    out4[b * 131072u + o4] = make_float4(0.f, 0.f, 0.f, 0.f);
}

__global__ void __launch_bounds__(512)
istft_fused_kernel(const float* __restrict__ spr,
                   const float* __restrict__ spi,
                   const float* __restrict__ win,
                   float* __restrict__ out)
{
    extern __shared__ float sm[];
    float2* A = (float2*)sm;    // 4096 float2 (FFT work buffer)
    float*  y = sm;             // frame staging overlays A: 8*YPITCH floats

    const int tid = threadIdx.x;
    const int f   = tid & 7;    // frame lane
    const int w   = tid >> 3;   // worker 0..63

    // register twiddle bases
    float zwr, zwi;   // e^{+2pi i w/1024}
    __sincosf((float)w * 6.1359231515e-3f, &zwi, &zwr);
    float w1r = fmaf(zwr, zwr, -zwi * zwi);   // e^{+2pi i w/512} = zw^2
    float w1i = 2.0f * zwr * zwi;
    const int h = w >> 3;
    float bhr, bhi;   // e^{+2pi i h/64}
    __sincosf((float)h * 9.8174770424e-2f, &bhi, &bhr);

    const int fr0 = blockIdx.x * FPB;
    const int b   = fr0 >> 11;
    const int t0  = fr0 & 2047;
    const float* pr  = spr + (size_t)b * NFREQ * TT + (t0 + f);
    const float* pim = spi + (size_t)b * NFREQ * TT + (t0 + f);

    // ---- load X[0..511] into A; X[512] in register on w==0 threads ----
    #pragma unroll
    for (int m = 0; m < 8; m++) {
        int k = w + (m << 6);
        float re = __ldg(pr  + k * TT);
        float im = __ldg(pim + k * TT);
        if (k == 0) im = 0.0f;
        A[sidx(k, f)] = make_float2(re, im);
    }
    float x512r = 0.0f;
    if (w == 0) x512r = __ldg(pr + 512 * TT);
    __syncthreads();

    float vr[8], vi[8];

    // ---- Hermitian packing Z[k]=E+iO (k = w+64m); twiddle chain from zw ----
    {
        const float S16r = 0.92387953251128675613f;  // e^{+2pi i/16}
        const float S16i = 0.38268343236508977173f;
        float ct = zwr, st = zwi;
        #pragma unroll
        for (int m = 0; m < 8; m++) {
            int k = w + (m << 6);
            float2 zk = A[sidx(k, f)];
            float xcr, xci;
            if (k == 0) { xcr = x512r; xci = 0.0f; }
            else        { float2 zc = A[sidx(512 - k, f)]; xcr = zc.x; xci = zc.y; }
            float Er = 0.5f * (zk.x + xcr);
            float Ei = 0.5f * (zk.y - xci);
            float Dr = 0.5f * (zk.x - xcr);
            float Di = 0.5f * (zk.y + xci);
            float Or = fmaf(ct, Dr, -st * Di);
            float Oi = fmaf(ct, Di,  st * Dr);
            vr[m] = Er - Oi;
            vi[m] = Ei + Or;
            float nc = fmaf(ct, S16r, -st * S16i);   // rotate by e^{2pi i/16}
            float ns = fmaf(ct, S16i,  st * S16r);
            ct = nc; st = ns;
        }
    }
    __syncthreads();   // packing reads done -> safe to overwrite A

    // ---- stage 1 (S=1): regs -> A, twiddle w1^m ----
    {
        float Xr[8], Xi[8];
        bfly8(vr, vi, Xr, Xi);
        A[sidx(8 * w, f)] = make_float2(Xr[0], Xi[0]);
        float cr = w1r, ci = w1i;
        #pragma unroll
        for (int m = 1; m < 8; m++) {
            A[sidx(8 * w + m, f)] =
                make_float2(fmaf(Xr[m], cr, -Xi[m] * ci),
                            fmaf(Xr[m], ci,  Xi[m] * cr));
            float nc = fmaf(cr, w1r, -ci * w1i);
            float ns = fmaf(cr, w1i,  ci * w1r);
            cr = nc; ci = ns;
        }
    }
    __syncthreads();

    // ---- stage 2 (S=8): A -> regs -> A, twiddle bh^m ----
    {
        #pragma unroll
        for (int j = 0; j < 8; j++) {
            float2 z = A[sidx(w + (j << 6), f)];
            vr[j] = z.x; vi[j] = z.y;
        }
        __syncthreads();
        float Xr[8], Xi[8];
        bfly8(vr, vi, Xr, Xi);
        const int wb = (w & 7) + 64 * h;
        A[sidx(wb, f)] = make_float2(Xr[0], Xi[0]);
        float cr = bhr, ci = bhi;
        #pragma unroll
        for (int m = 1; m < 8; m++) {
            A[sidx(wb + 8 * m, f)] =
                make_float2(fmaf(Xr[m], cr, -Xi[m] * ci),
                            fmaf(Xr[m], ci,  Xi[m] * cr));
            float nc = fmaf(cr, bhr, -ci * bhi);
            float ns = fmaf(cr, bhi,  ci * bhr);
            cr = nc; ci = ns;
        }
    }
    __syncthreads();

    // ---- stage 3 (S=64): A -> regs; windowed frames -> y[f][pos] ----
    #pragma unroll
    for (int j = 0; j < 8; j++) {
        float2 z = A[sidx(w + (j << 6), f)];
        vr[j] = z.x; vi[j] = z.y;
    }
    __syncthreads();   // reads done -> y may overwrite A
    {
        float Xr[8], Xi[8];
        bfly8(vr, vi, Xr, Xi);
        const float2* w2 = (const float2*)win;
        const float inv = 1.0f / 512.0f;
        float* yf = y + f * YPITCH;
        #pragma unroll
        for (int m = 0; m < 8; m++) {
            int n = w + (m << 6);
            float2 wv = __ldg(w2 + n);
            float2 o;
            o.x = Xr[m] * inv * wv.x;
            o.y = Xi[m] * inv * wv.y;
            *(float2*)(yf + 2 * n) = o;        // pos 2n, 2n+1
        }
    }
    __syncthreads();

    // =================== overlap-add from shared ===================
    float* outb = out + (size_t)b * OUT_PER_B;
    const float TW3 = 2.0f / 3.0f;

    // interior-owned: tmax in [t0+3, t0+7]; 1280 samples as 640 float2
    for (int s2 = tid; s2 < 640; s2 += 512) {
        int fl  = 3 + (s2 >> 7);           // tmax - t0, 3..7
        int pos = (s2 & 127) << 1;         // 0..254 even
        const float* yb = y + pos;
        float2 a0 = *(const float2*)(yb + (fl - 3) * YPITCH + 768);
        float2 a1 = *(const float2*)(yb + (fl - 2) * YPITCH + 512);
        float2 a2 = *(const float2*)(yb + (fl - 1) * YPITCH + 256);
        float2 a3 = *(const float2*)(yb +  fl      * YPITCH);
        float2 r;
        r.x = (a0.x + a1.x + a2.x + a3.x) * TW3;
        r.y = (a0.y + a1.y + a2.y + a3.y) * TW3;
        *(float2*)(outb + ((t0 + fl) << 8) + pos - PAD) = r;
    }

    if (t0 != 0) {
        // bottom stripe: l in [256 t0, 256 t0 + 768)
        for (int s = tid; s < 768; s += 512) {
            int r = s >> 8;                // tmax - t0: 0,1,2
            float acc = y[s];
            if (r >= 1) acc += y[1 * YPITCH + s - 256];
            if (r >= 2) acc += y[2 * YPITCH + s - 512];
            atomicAdd(outb + (t0 << 8) + s - PAD, acc * TW3);
        }
    } else {
        // batch start: l in [384, 768), env varies
        if (tid < 384) {
            int l = PAD + tid;
            int tmax = l >> 8;             // 1 or 2
            float acc = 0.0f, env = 0.0f;
            for (int t = 0; t <= tmax; t++) {
                int pos = l - (t << 8);
                float wv = __ldg(win + pos);
                env = fmaf(wv, wv, env);
                acc += y[t * YPITCH + pos];
            }
            outb[l - PAD] = acc / env;
        }
    }

    if (t0 != 2040) {
        // top stripe: l in [256(t0+8), +768)
        for (int s = tid; s < 768; s += 512) {
            int r = s >> 8;                // 0,1,2 ; count = 3 - r
            float acc = y[7 * YPITCH + s + 256];
            if (r <= 1) acc += y[6 * YPITCH + s + 512];
            if (r == 0) acc += y[5 * YPITCH + s + 768];
            atomicAdd(outb + ((t0 + 8) << 8) + s - PAD, acc * TW3);
        }
    } else {
        // batch end: l in [524288, 524672)
        if (tid < 384) {
            int l = 524288 + tid;
            int tmin = (l - 768) >> 8;     // 2045..2046
            float acc = 0.0f, env = 0.0f;
            for (int t = tmin; t <= 2047; t++) {
                int pos = l - (t << 8);
                float wv = __ldg(win + pos);
                env = fmaf(wv, wv, env);
                acc += y[(t - 2040) * YPITCH + pos];
            }
            outb[l - PAD] = acc / env;
        }
    }
}

extern "C" void kernel_launch(void* const* d_in, const int* in_sizes, int n_in,
                              void* d_out, int out_size)
{
    const float* spr = (const float*)d_in[0];
    const float* spi = (const float*)d_in[1];
    const float* win = (const float*)d_in[2];
    float* out = (float*)d_out;

    cudaFuncSetAttribute(istft_fused_kernel,
                         cudaFuncAttributeMaxDynamicSharedMemorySize, SM_BYTES);

    istft_zero_kernel<<<3072, 256>>>((float4*)out);
    istft_fused_kernel<<<NFRAMES / FPB, 512, SM_BYTES>>>(spr, spi, win, out);
}

// round 13
// speedup vs baseline: 1.6307x; 1.0202x over previous
#include <cuda_runtime.h>

// ---------------------------------------------------------------------------
// ISTFT fused: B=16, NFREQ=513, T=2048, NFFT=1024, HOP=256, WIN=1024, PAD=384
// Kernel A: zero exactly the atomic-stripe samples (compact index mapping).
// Kernel B: 8 frames/block, real-packed 512-pt radix-8 Stockham inverse FFT
//           with float2-interleaved shared (LDS.64/STS.64, conflict-free
//           swizzle) and register-computed twiddles; windowed frames staged
//           in shared; overlap-add direct to out (float2 stores interior,
//           2-way atomicAdd stripes, explicit env at batch edges).
//           __launch_bounds__(512,4) pins 4 blocks/SM (<=32 regs).
// ---------------------------------------------------------------------------

#define BATCH     16
#define NFREQ     513
#define TT        2048
#define NFFT      1024
#define HOP       256
#define PAD       384
#define OUT_PER_B 524288                 // (T-1)*HOP + WIN - 2*PAD = 1<<19
#define NFRAMES   (BATCH * TT)           // 32768
#define FPB       8                      // frames per block
#define YPITCH    1028                   // 1028 % 32 == 4 -> bank-perm rows

#define SM_FLOATS (FPB * YPITCH + 8)     // max(A: 8192, y: 8224)
#define SM_BYTES  (SM_FLOATS * 4)        // 32928 bytes

// conflict-free shared index (float2 units): phi(pos) = pos ^ (pos>>3)
__device__ __forceinline__ int sidx(int pos, int f) {
    return ((pos ^ (pos >> 3)) << 3) | f;
}

// radix-8 butterfly on 8 complex registers (inverse FFT, +i convention)
__device__ __forceinline__ void bfly8(const float* xr, const float* xi,
                                      float* Xr, float* Xi)
{
    float e0r = xr[0] + xr[4], e0i = xi[0] + xi[4];
    float e1r = xr[0] - xr[4], e1i = xi[0] - xi[4];
    float e2r = xr[2] + xr[6], e2i = xi[2] + xi[6];
    float e3r = xr[2] - xr[6], e3i = xi[2] - xi[6];
    float E0r = e0r + e2r, E0i = e0i + e2i;
    float E2r = e0r - e2r, E2i = e0i - e2i;
    float E1r = e1r - e3i, E1i = e1i + e3r;
    float E3r = e1r + e3i, E3i = e1i - e3r;

    float o0r = xr[1] + xr[5], o0i = xi[1] + xi[5];
    float o1r = xr[1] - xr[5], o1i = xi[1] - xi[5];
    float o2r = xr[3] + xr[7], o2i = xi[3] + xi[7];
    float o3r = xr[3] - xr[7], o3i = xi[3] - xi[7];
    float O0r = o0r + o2r, O0i = o0i + o2i;
    float O2r = o0r - o2r, O2i = o0i - o2i;
    float O1r = o1r - o3i, O1i = o1i + o3r;
    float O3r = o1r + o3i, O3i = o1i - o3r;

    const float RS = 0.70710678118654752440f;
    float c1r = RS * (O1r - O1i), c1i = RS * (O1r + O1i);   // e^{+i pi/4} O1
    float c2r = -O2i,             c2i = O2r;                // i * O2
    float c3r = -RS * (O3r + O3i), c3i = RS * (O3r - O3i);  // e^{+3i pi/4} O3

    Xr[0] = E0r + O0r; Xi[0] = E0i + O0i;
    Xr[4] = E0r - O0r; Xi[4] = E0i - O0i;
    Xr[1] = E1r + c1r; Xi[1] = E1i + c1i;
    Xr[5] = E1r - c1r; Xi[5] = E1i - c1i;
    Xr[2] = E2r + c2r; Xi[2] = E2i + c2i;
    Xr[6] = E2r - c2r; Xi[6] = E2i - c2i;
    Xr[3] = E3r + c3r; Xi[3] = E3i + c3i;
    Xr[7] = E3r - c3r; Xi[7] = E3i - c3i;
}

// zero exactly the stripe float4s: per batch 96 + 255*192 + 96 = 49152
__global__ void __launch_bounds__(256)
istft_zero_kernel(float4* __restrict__ out4)
{
    unsigned idx = blockIdx.x * 256u + threadIdx.x;   // < 786432
    unsigned b = idx / 49152u;
    unsigned r = idx - b * 49152u;
    unsigned o4;
    if (r < 96u) {
        o4 = r;                                       // head: o in [0,384)
    } else {
        unsigned rr = r - 96u;
        unsigned k  = rr / 192u + 1u;                 // 8-frame period 1..256
        unsigned j  = rr - (k - 1u) * 192u;
        o4 = (k << 9) - 96u + j;                      // o in [2048k-384, +768)
    }
    out4[b * 131072u + o4] = make_float4(0.f, 0.f, 0.f, 0.f);
}

__global__ void __launch_bounds__(512, 4)
istft_fused_kernel(const float* __restrict__ spr,
                   const float* __restrict__ spi,
                   const float* __restrict__ win,
                   float* __restrict__ out)
{
    extern __shared__ float sm[];
    float2* A = (float2*)sm;    // 4096 float2 (FFT work buffer)
    float*  y = sm;             // frame staging overlays A: 8*YPITCH floats

    const int tid = threadIdx.x;
    const int f   = tid & 7;    // frame lane
    const int w   = tid >> 3;   // worker 0..63

    // register twiddle bases
    float zwr, zwi;   // e^{+2pi i w/1024}
    __sincosf((float)w * 6.1359231515e-3f, &zwi, &zwr);
    float w1r = fmaf(zwr, zwr, -zwi * zwi);   // e^{+2pi i w/512} = zw^2
    float w1i = 2.0f * zwr * zwi;
    const int h = w >> 3;
    float bhr, bhi;   // e^{+2pi i h/64}
    __sincosf((float)h * 9.8174770424e-2f, &bhi, &bhr);

    const int fr0 = blockIdx.x * FPB;
    const int b   = fr0 >> 11;
    const int t0  = fr0 & 2047;
    const float* pr  = spr + (size_t)b * NFREQ * TT + (t0 + f);
    const float* pim = spi + (size_t)b * NFREQ * TT + (t0 + f);

    // ---- load X[0..511] into A; X[512] in register on w==0 threads ----
    #pragma unroll
    for (int m = 0; m < 8; m++) {
        int k = w + (m << 6);
        float re = __ldg(pr  + k * TT);
        float im = __ldg(pim + k * TT);
        if (k == 0) im = 0.0f;
        A[sidx(k, f)] = make_float2(re, im);
    }
    float x512r = 0.0f;
    if (w == 0) x512r = __ldg(pr + 512 * TT);
    __syncthreads();

    float vr[8], vi[8];

    // ---- Hermitian packing Z[k]=E+iO (k = w+64m); twiddle chain from zw ----
    {
        const float S16r = 0.92387953251128675613f;  // e^{+2pi i/16}
        const float S16i = 0.38268343236508977173f;
        float ct = zwr, st = zwi;
        #pragma unroll
        for (int m = 0; m < 8; m++) {
            int k = w + (m << 6);
            float2 zk = A[sidx(k, f)];
            float xcr, xci;
            if (k == 0) { xcr = x512r; xci = 0.0f; }
            else        { float2 zc = A[sidx(512 - k, f)]; xcr = zc.x; xci = zc.y; }
            float Er = 0.5f * (zk.x + xcr);
            float Ei = 0.5f * (zk.y - xci);
            float Dr = 0.5f * (zk.x - xcr);
            float Di = 0.5f * (zk.y + xci);
            float Or = fmaf(ct, Dr, -st * Di);
            float Oi = fmaf(ct, Di,  st * Dr);
            vr[m] = Er - Oi;
            vi[m] = Ei + Or;
            float nc = fmaf(ct, S16r, -st * S16i);   // rotate by e^{2pi i/16}
            float ns = fmaf(ct, S16i,  st * S16r);
            ct = nc; st = ns;
        }
    }
    __syncthreads();   // packing reads done -> safe to overwrite A

    // ---- stage 1 (S=1): regs -> A, twiddle w1^m ----
    {
        float Xr[8], Xi[8];
        bfly8(vr, vi, Xr, Xi);
        A[sidx(8 * w, f)] = make_float2(Xr[0], Xi[0]);
        float cr = w1r, ci = w1i;
        #pragma unroll
        for (int m = 1; m < 8; m++) {
            A[sidx(8 * w + m, f)] =
                make_float2(fmaf(Xr[m], cr, -Xi[m] * ci),
                            fmaf(Xr[m], ci,  Xi[m] * cr));
            float nc = fmaf(cr, w1r, -ci * w1i);
            float ns = fmaf(cr, w1i,  ci * w1r);
            cr = nc; ci = ns;
        }
    }
    __syncthreads();

    // ---- stage 2 (S=8): A -> regs -> A, twiddle bh^m ----
    {
        #pragma unroll
        for (int j = 0; j < 8; j++) {
            float2 z = A[sidx(w + (j << 6), f)];
            vr[j] = z.x; vi[j] = z.y;
        }
        __syncthreads();
        float Xr[8], Xi[8];
        bfly8(vr, vi, Xr, Xi);
        const int wb = (w & 7) + 64 * h;
        A[sidx(wb, f)] = make_float2(Xr[0], Xi[0]);
        float cr = bhr, ci = bhi;
        #pragma unroll
        for (int m = 1; m < 8; m++) {
            A[sidx(wb + 8 * m, f)] =
                make_float2(fmaf(Xr[m], cr, -Xi[m] * ci),
                            fmaf(Xr[m], ci,  Xi[m] * cr));
            float nc = fmaf(cr, bhr, -ci * bhi);
            float ns = fmaf(cr, bhi,  ci * bhr);
            cr = nc; ci = ns;
        }
    }
    __syncthreads();

    // ---- stage 3 (S=64): A -> regs; windowed frames -> y[f][pos] ----
    #pragma unroll
    for (int j = 0; j < 8; j++) {
        float2 z = A[sidx(w + (j << 6), f)];
        vr[j] = z.x; vi[j] = z.y;
    }
    __syncthreads();   // reads done -> y may overwrite A
    {
        float Xr[8], Xi[8];
        bfly8(vr, vi, Xr, Xi);
        const float2* w2 = (const float2*)win;
        const float inv = 1.0f / 512.0f;
        float* yf = y + f * YPITCH;
        #pragma unroll
        for (int m = 0; m < 8; m++) {
            int n = w + (m << 6);
            float2 wv = __ldg(w2 + n);
            float2 o;
            o.x = Xr[m] * inv * wv.x;
            o.y = Xi[m] * inv * wv.y;
            *(float2*)(yf + 2 * n) = o;        // pos 2n, 2n+1
        }
    }
    __syncthreads();

    // =================== overlap-add from shared ===================
    float* outb = out + (size_t)b * OUT_PER_B;
    const float TW3 = 2.0f / 3.0f;

    // interior-owned: tmax in [t0+3, t0+7]; 1280 samples as 640 float2
    for (int s2 = tid; s2 < 640; s2 += 512) {
        int fl  = 3 + (s2 >> 7);           // tmax - t0, 3..7
        int pos = (s2 & 127) << 1;         // 0..254 even
        const float* yb = y + pos;
        float2 a0 = *(const float2*)(yb + (fl - 3) * YPITCH + 768);
        float2 a1 = *(const float2*)(yb + (fl - 2) * YPITCH + 512);
        float2 a2 = *(const float2*)(yb + (fl - 1) * YPITCH + 256);
        float2 a3 = *(const float2*)(yb +  fl      * YPITCH);
        float2 r;
        r.x = (a0.x + a1.x + a2.x + a3.x) * TW3;
        r.y = (a0.y + a1.y + a2.y + a3.y) * TW3;
        *(float2*)(outb + ((t0 + fl) << 8) + pos - PAD) = r;
    }

    if (t0 != 0) {
        // bottom stripe: l in [256 t0, 256 t0 + 768)
        for (int s = tid; s < 768; s += 512) {
            int r = s >> 8;                // tmax - t0: 0,1,2
            float acc = y[s];
            if (r >= 1) acc += y[1 * YPITCH + s - 256];
            if (r >= 2) acc += y[2 * YPITCH + s - 512];
            atomicAdd(outb + (t0 << 8) + s - PAD, acc * TW3);
        }
    } else {
        // batch start: l in [384, 768), env varies
        if (tid < 384) {
            int l = PAD + tid;
            int tmax = l >> 8;             // 1 or 2
            float acc = 0.0f, env = 0.0f;
            for (int t = 0; t <= tmax; t++) {
                int pos = l - (t << 8);
                float wv = __ldg(win + pos);
                env = fmaf(wv, wv, env);
                acc += y[t * YPITCH + pos];
            }
            outb[l - PAD] = acc / env;
        }
    }

    if (t0 != 2040) {
        // top stripe: l in [256(t0+8), +768)
        for (int s = tid; s < 768; s += 512) {
            int r = s >> 8;                // 0,1,2 ; count = 3 - r
            float acc = y[7 * YPITCH + s + 256];
            if (r <= 1) acc += y[6 * YPITCH + s + 512];
            if (r == 0) acc += y[5 * YPITCH + s + 768];
            atomicAdd(outb + ((t0 + 8) << 8) + s - PAD, acc * TW3);
        }
    } else {
        // batch end: l in [524288, 524672)
        if (tid < 384) {
            int l = 524288 + tid;
            int tmin = (l - 768) >> 8;     // 2045..2046
            float acc = 0.0f, env = 0.0f;
            for (int t = tmin; t <= 2047; t++) {
                int pos = l - (t << 8);
                float wv = __ldg(win + pos);
                env = fmaf(wv, wv, env);
                acc += y[(t - 2040) * YPITCH + pos];
            }
            outb[l - PAD] = acc / env;
        }
    }
}

extern "C" void kernel_launch(void* const* d_in, const int* in_sizes, int n_in,
                              void* d_out, int out_size)
{
    const float* spr = (const float*)d_in[0];
    const float* spi = (const float*)d_in[1];
    const float* win = (const float*)d_in[2];
    float* out = (float*)d_out;

    cudaFuncSetAttribute(istft_fused_kernel,
                         cudaFuncAttributeMaxDynamicSharedMemorySize, SM_BYTES);

    istft_zero_kernel<<<3072, 256>>>((float4*)out);
    istft_fused_kernel<<<NFRAMES / FPB, 512, SM_BYTES>>>(spr, spi, win, out);
}

// round 15
// speedup vs baseline: 1.7351x; 1.0640x over previous
#include <cuda_runtime.h>

// ---------------------------------------------------------------------------
// ISTFT fused: B=16, NFREQ=513, T=2048, NFFT=1024, HOP=256, WIN=1024, PAD=384
// Kernel A: zero exactly the atomic-stripe samples (compact index mapping).
// Kernel B: 8 frames/block, real-packed 512-pt radix-8 Stockham inverse FFT.
//           Shared layout uses ADDITIVE padding idx = pos + (pos>>3) (affine
//           in pos -> all shared addresses are base+immediate; verified
//           conflict-free for every access pattern), register twiddles,
//           windowed frames staged in shared, overlap-add direct to out
//           (float4 interior stores, 2-way atomicAdd stripes, explicit env
//           at batch edges). __launch_bounds__(512,4) pins 4 blocks/SM.
// ---------------------------------------------------------------------------

#define BATCH     16
#define NFREQ     513
#define TT        2048
#define NFFT      1024
#define HOP       256
#define PAD       384
#define OUT_PER_B 524288                 // (T-1)*HOP + WIN - 2*PAD = 1<<19
#define NFRAMES   (BATCH * TT)           // 32768
#define FPB       8                      // frames per block
#define YPITCH    1028                   // 1028 % 32 == 4 -> bank-perm rows

// A: 577 padded slots x 8 frames float2 = 9232 floats; y: 8224 floats (fits)
#define SM_FLOATS 9232
#define SM_BYTES  (SM_FLOATS * 4)        // 36928 bytes -> 4 blocks/SM

// radix-8 butterfly on 8 complex registers (inverse FFT, +i convention)
__device__ __forceinline__ void bfly8(const float* xr, const float* xi,
                                      float* Xr, float* Xi)
{
    float e0r = xr[0] + xr[4], e0i = xi[0] + xi[4];
    float e1r = xr[0] - xr[4], e1i = xi[0] - xi[4];
    float e2r = xr[2] + xr[6], e2i = xi[2] + xi[6];
    float e3r = xr[2] - xr[6], e3i = xi[2] - xi[6];
    float E0r = e0r + e2r, E0i = e0i + e2i;
    float E2r = e0r - e2r, E2i = e0i - e2i;
    float E1r = e1r - e3i, E1i = e1i + e3r;
    float E3r = e1r + e3i, E3i = e1i - e3r;

    float o0r = xr[1] + xr[5], o0i = xi[1] + xi[5];
    float o1r = xr[1] - xr[5], o1i = xi[1] - xi[5];
    float o2r = xr[3] + xr[7], o2i = xi[3] + xi[7];
    float o3r = xr[3] - xr[7], o3i = xi[3] - xi[7];
    float O0r = o0r + o2r, O0i = o0i + o2i;
    float O2r = o0r - o2r, O2i = o0i - o2i;
    float O1r = o1r - o3i, O1i = o1i + o3r;
    float O3r = o1r + o3i, O3i = o1i - o3r;

    const float RS = 0.70710678118654752440f;
    float c1r = RS * (O1r - O1i), c1i = RS * (O1r + O1i);   // e^{+i pi/4} O1
    float c2r = -O2i,             c2i = O2r;                // i * O2
    float c3r = -RS * (O3r + O3i), c3i = RS * (O3r - O3i);  // e^{+3i pi/4} O3

    Xr[0] = E0r + O0r; Xi[0] = E0i + O0i;
    Xr[4] = E0r - O0r; Xi[4] = E0i - O0i;
    Xr[1] = E1r + c1r; Xi[1] = E1i + c1i;
    Xr[5] = E1r - c1r; Xi[5] = E1i - c1i;
    Xr[2] = E2r + c2r; Xi[2] = E2i + c2i;
    Xr[6] = E2r - c2r; Xi[6] = E2i - c2i;
    Xr[3] = E3r + c3r; Xi[3] = E3i + c3i;
    Xr[7] = E3r - c3r; Xi[7] = E3i - c3i;
}

// zero exactly the stripe float4s: per batch 96 + 255*192 + 96 = 49152
__global__ void __launch_bounds__(256)
istft_zero_kernel(float4* __restrict__ out4)
{
    unsigned idx = blockIdx.x * 256u + threadIdx.x;   // < 786432
    unsigned b = idx / 49152u;
    unsigned r = idx - b * 49152u;
    unsigned o4;
    if (r < 96u) {
        o4 = r;                                       // head: o in [0,384)
    } else {
        unsigned rr = r - 96u;
        unsigned k  = rr / 192u + 1u;                 // 8-frame period 1..256
        unsigned j  = rr - (k - 1u) * 192u;
        o4 = (k << 9) - 96u + j;                      // o in [2048k-384, +768)
    }
    out4[b * 131072u + o4] = make_float4(0.f, 0.f, 0.f, 0.f);
}

__global__ void __launch_bounds__(512, 4)
istft_fused_kernel(const float* __restrict__ spr,
                   const float* __restrict__ spi,
                   const float* __restrict__ win,
                   float* __restrict__ out)
{
    extern __shared__ float sm[];
    float2* A = (float2*)sm;    // padded FFT buffer: A[idx(pos)*8 + f]
    float*  y = sm;             // frame staging overlays A: 8*YPITCH floats

    const int tid = threadIdx.x;
    const int f   = tid & 7;    // frame lane
    const int w   = tid >> 3;   // worker 0..63

    // affine address bases (all shared accesses become base + immediate)
    const int iw  = w + (w >> 3);                 // idx(w + 64j) = iw + 72j
    const int imw = 575 - w - ((w - 1) >> 3);     // idx(512-w-64m) = imw - 72m
    float2* Aw  = A + iw * 8 + f;                 // stage/spectrum base
    float2* Amw = A + imw * 8 + f;                // mirror base
    float2* As1 = A + (9 * w) * 8 + f;            // stage-1 write base
    const int h = w >> 3;
    float2* As2 = A + (72 * h + (w & 7)) * 8 + f; // stage-2 write base

    // register twiddle bases
    float zwr, zwi;   // e^{+2pi i w/1024}
    __sincosf((float)w * 6.1359231515e-3f, &zwi, &zwr);
    float w1r = fmaf(zwr, zwr, -zwi * zwi);   // e^{+2pi i w/512}
    float w1i = 2.0f * zwr * zwi;
    float bhr, bhi;   // e^{+2pi i h/64}
    __sincosf((float)h * 9.8174770424e-2f, &bhi, &bhr);

    const int fr0 = blockIdx.x * FPB;
    const int b   = fr0 >> 11;
    const int t0  = fr0 & 2047;
    const float* pr  = spr + (size_t)b * NFREQ * TT + (t0 + f);
    const float* pim = spi + (size_t)b * NFREQ * TT + (t0 + f);

    // ---- load X[0..511] into A; X[512] in register on w==0 threads ----
    #pragma unroll
    for (int m = 0; m < 8; m++) {
        int k = w + (m << 6);
        float re = __ldg(pr  + k * TT);
        float im = __ldg(pim + k * TT);
        if (k == 0) im = 0.0f;
        Aw[576 * m] = make_float2(re, im);     // idx step 72 -> float2 step 576
    }
    float x512r = 0.0f;
    if (w == 0) x512r = __ldg(pr + 512 * TT);
    __syncthreads();

    float vr[8], vi[8];

    // ---- Hermitian packing Z[k]=E+iO (k = w+64m); twiddle chain from zw ----
    {
        const float S16r = 0.92387953251128675613f;  // e^{+2pi i/16}
        const float S16i = 0.38268343236508977173f;
        float ct = zwr, st = zwi;
        #pragma unroll
        for (int m = 0; m < 8; m++) {
            float2 zk = Aw[576 * m];
            float xcr, xci;
            if (w == 0 && m == 0) { xcr = x512r; xci = 0.0f; }
            else { float2 zc = Amw[-576 * m]; xcr = zc.x; xci = zc.y; }
            float Er = 0.5f * (zk.x + xcr);
            float Ei = 0.5f * (zk.y - xci);
            float Dr = 0.5f * (zk.x - xcr);
            float Di = 0.5f * (zk.y + xci);
            float Or = fmaf(ct, Dr, -st * Di);
            float Oi = fmaf(ct, Di,  st * Dr);
            vr[m] = Er - Oi;
            vi[m] = Ei + Or;
            float nc = fmaf(ct, S16r, -st * S16i);   // rotate by e^{2pi i/16}
            float ns = fmaf(ct, S16i,  st * S16r);
            ct = nc; st = ns;
        }
    }
    __syncthreads();   // packing reads done -> safe to overwrite A

    // ---- stage 1 (S=1): regs -> A at idx 9w+m, twiddle w1^m ----
    {
        float Xr[8], Xi[8];
        bfly8(vr, vi, Xr, Xi);
        As1[0] = make_float2(Xr[0], Xi[0]);
        float cr = w1r, ci = w1i;
        #pragma unroll
        for (int m = 1; m < 8; m++) {
            As1[8 * m] = make_float2(fmaf(Xr[m], cr, -Xi[m] * ci),
                                     fmaf(Xr[m], ci,  Xi[m] * cr));
            float nc = fmaf(cr, w1r, -ci * w1i);
            float ns = fmaf(cr, w1i,  ci * w1r);
            cr = nc; ci = ns;
        }
    }
    __syncthreads();

    // ---- stage 2 (S=8): A -> regs -> A at idx 72h+q+9m, twiddle bh^m ----
    {
        #pragma unroll
        for (int j = 0; j < 8; j++) {
            float2 z = Aw[576 * j];
            vr[j] = z.x; vi[j] = z.y;
        }
        __syncthreads();
        float Xr[8], Xi[8];
        bfly8(vr, vi, Xr, Xi);
        As2[0] = make_float2(Xr[0], Xi[0]);
        float cr = bhr, ci = bhi;
        #pragma unroll
        for (int m = 1; m < 8; m++) {
            As2[72 * m] = make_float2(fmaf(Xr[m], cr, -Xi[m] * ci),
                                      fmaf(Xr[m], ci,  Xi[m] * cr));
            float nc = fmaf(cr, bhr, -ci * bhi);
            float ns = fmaf(cr, bhi,  ci * bhr);
            cr = nc; ci = ns;
        }
    }
    __syncthreads();

    // ---- stage 3 (S=64): A -> regs; windowed frames -> y[f][pos] ----
    #pragma unroll
    for (int j = 0; j < 8; j++) {
        float2 z = Aw[576 * j];
        vr[j] = z.x; vi[j] = z.y;
    }
    __syncthreads();   // reads done -> y may overwrite A
    {
        float Xr[8], Xi[8];
        bfly8(vr, vi, Xr, Xi);
        const float2* w2 = (const float2*)win;
        const float inv = 1.0f / 512.0f;
        float* yf = y + f * YPITCH + 2 * w;
        #pragma unroll
        for (int m = 0; m < 8; m++) {
            float2 wv = __ldg(w2 + w + (m << 6));
            float2 o;
            o.x = Xr[m] * inv * wv.x;
            o.y = Xi[m] * inv * wv.y;
            *(float2*)(yf + 128 * m) = o;      // pos 2n, 2n+1 (n = w + 64m)
        }
    }
    __syncthreads();

    // =================== overlap-add from shared ===================
    float* outb = out + (size_t)b * OUT_PER_B;
    const float TW3 = 2.0f / 3.0f;

    // interior-owned: tmax in [t0+3, t0+7]; 1280 samples as 320 float4
    if (tid < 320) {
        int fl  = 3 + (tid >> 6);          // tmax - t0, 3..7
        int pos = (tid & 63) << 2;         // 0..252, step 4
        const float* yb = y + pos;
        float4 a0 = *(const float4*)(yb + (fl - 3) * YPITCH + 768);
        float4 a1 = *(const float4*)(yb + (fl - 2) * YPITCH + 512);
        float4 a2 = *(const float4*)(yb + (fl - 1) * YPITCH + 256);
        float4 a3 = *(const float4*)(yb +  fl      * YPITCH);
        float4 r;
        r.x = (a0.x + a1.x + a2.x + a3.x) * TW3;
        r.y = (a0.y + a1.y + a2.y + a3.y) * TW3;
        r.z = (a0.z + a1.z + a2.z + a3.z) * TW3;
        r.w = (a0.w + a1.w + a2.w + a3.w) * TW3;
        *(float4*)(outb + ((t0 + fl) << 8) + pos - PAD) = r;
    }

    if (t0 != 0) {
        // bottom stripe: l in [256 t0, 256 t0 + 768)
        for (int s = tid; s < 768; s += 512) {
            int r = s >> 8;                // tmax - t0: 0,1,2
            float acc = y[s];
            if (r >= 1) acc += y[1 * YPITCH + s - 256];
            if (r >= 2) acc += y[2 * YPITCH + s - 512];
            atomicAdd(outb + (t0 << 8) + s - PAD, acc * TW3);
        }
    } else {
        // batch start: l in [384, 768), env varies
        if (tid < 384) {
            int l = PAD + tid;
            int tmax = l >> 8;             // 1 or 2
            float acc = 0.0f, env = 0.0f;
            for (int t = 0; t <= tmax; t++) {
                int pos = l - (t << 8);
                float wv = __ldg(win + pos);
                env = fmaf(wv, wv, env);
                acc += y[t * YPITCH + pos];
            }
            outb[l - PAD] = acc / env;
        }
    }

    if (t0 != 2040) {
        // top stripe: l in [256(t0+8), +768)
        for (int s = tid; s < 768; s += 512) {
            int r = s >> 8;                // 0,1,2 ; count = 3 - r
            float acc = y[7 * YPITCH + s + 256];
            if (r <= 1) acc += y[6 * YPITCH + s + 512];
            if (r == 0) acc += y[5 * YPITCH + s + 768];
            atomicAdd(outb + ((t0 + 8) << 8) + s - PAD, acc * TW3);
        }
    } else {
        // batch end: l in [524288, 524672)
        if (tid < 384) {
            int l = 524288 + tid;
            int tmin = (l - 768) >> 8;     // 2045..2046
            float acc = 0.0f, env = 0.0f;
            for (int t = tmin; t <= 2047; t++) {
                int pos = l - (t << 8);
                float wv = __ldg(win + pos);
                env = fmaf(wv, wv, env);
                acc += y[(t - 2040) * YPITCH + pos];
            }
            outb[l - PAD] = acc / env;
        }
    }
}

extern "C" void kernel_launch(void* const* d_in, const int* in_sizes, int n_in,
                              void* d_out, int out_size)
{
    const float* spr = (const float*)d_in[0];
    const float* spi = (const float*)d_in[1];
    const float* win = (const float*)d_in[2];
    float* out = (float*)d_out;

    cudaFuncSetAttribute(istft_fused_kernel,
                         cudaFuncAttributeMaxDynamicSharedMemorySize, SM_BYTES);

    istft_zero_kernel<<<3072, 256>>>((float4*)out);
    istft_fused_kernel<<<NFRAMES / FPB, 512, SM_BYTES>>>(spr, spi, win, out);
}